// round 1
// baseline (speedup 1.0000x reference)
#include <cuda_runtime.h>
#include <cuda_bf16.h>
#include <cstdint>

#define NN   50000
#define F_IN 256
#define HID  128
#define NH   8
#define DH   16
#define EE   800000
#define MM   3
#define OUTD 8

// ---------------- scratch (device globals; no allocation) ----------------
__device__ float d_h [NN * HID];
__device__ float d_fs[NN * HID];
__device__ float d_fd[NN * HID];
__device__ float d_el[NN * NH];
__device__ float d_er[NN * NH];
__device__ float d_ss[NN * NH];
__device__ float d_ex[EE * NH];
__device__ float d_z [NN * MM * HID];
__device__ float d_t [NN * MM * HID];
__device__ float d_w [NN * MM];

// ---------------- generic 128-col SGEMM: C = act(A@B + bias) ----------------
// A: (Mrows, K) row-major, B: (K, 128) row-major, C: (Mrows, 128)
// act: 0 = none, 1 = tanh
#define BM 64
#define BK 16
__global__ void __launch_bounds__(256) sgemm128(
    const float* __restrict__ A, const float* __restrict__ B,
    const float* __restrict__ bias, float* __restrict__ C,
    int Mrows, int K, int act)
{
    __shared__ float As[BK][BM];
    __shared__ float Bs[BK][HID];
    const int tid = threadIdx.x;
    const int tx = tid & 15;      // 16 col groups * 8 = 128
    const int ty = tid >> 4;      // 16 row groups * 4 = 64
    const int rowBase = blockIdx.x * BM;

    const int arow = tid >> 2;          // 0..63
    const int acol = (tid & 3) * 4;     // 0,4,8,12
    const int brow = tid >> 5;          // 0..7
    const int bcol = (tid & 31) * 4;    // 0..124

    float acc[4][8];
#pragma unroll
    for (int i = 0; i < 4; i++)
#pragma unroll
        for (int j = 0; j < 8; j++) acc[i][j] = 0.f;

    for (int k0 = 0; k0 < K; k0 += BK) {
        int gr = rowBase + arow;
        float4 av = make_float4(0.f, 0.f, 0.f, 0.f);
        if (gr < Mrows)
            av = *reinterpret_cast<const float4*>(A + (size_t)gr * K + k0 + acol);
        As[acol + 0][arow] = av.x;
        As[acol + 1][arow] = av.y;
        As[acol + 2][arow] = av.z;
        As[acol + 3][arow] = av.w;
#pragma unroll
        for (int r = 0; r < 2; r++) {
            int kb = brow + r * 8;
            float4 bv = *reinterpret_cast<const float4*>(B + (size_t)(k0 + kb) * HID + bcol);
            *reinterpret_cast<float4*>(&Bs[kb][bcol]) = bv;
        }
        __syncthreads();
#pragma unroll
        for (int kk = 0; kk < BK; kk++) {
            float a[4], b[8];
#pragma unroll
            for (int i = 0; i < 4; i++) a[i] = As[kk][ty * 4 + i];
            float4 b0 = *reinterpret_cast<const float4*>(&Bs[kk][tx * 8]);
            float4 b1 = *reinterpret_cast<const float4*>(&Bs[kk][tx * 8 + 4]);
            b[0]=b0.x; b[1]=b0.y; b[2]=b0.z; b[3]=b0.w;
            b[4]=b1.x; b[5]=b1.y; b[6]=b1.z; b[7]=b1.w;
#pragma unroll
            for (int i = 0; i < 4; i++)
#pragma unroll
                for (int j = 0; j < 8; j++) acc[i][j] += a[i] * b[j];
        }
        __syncthreads();
    }
#pragma unroll
    for (int i = 0; i < 4; i++) {
        int r = rowBase + ty * 4 + i;
        if (r >= Mrows) break;
#pragma unroll
        for (int j = 0; j < 8; j++) {
            int c = tx * 8 + j;
            float v = acc[i][j];
            if (bias) v += bias[c];
            if (act == 1) v = tanhf(v);
            C[(size_t)r * HID + c] = v;
        }
    }
}

// ---------------- per-node attention logits el/er + ssum zero ----------------
__global__ void elr_kernel(const float* __restrict__ fs, const float* __restrict__ fd,
                           const float* __restrict__ al, const float* __restrict__ ar,
                           float* __restrict__ el, float* __restrict__ er,
                           float* __restrict__ ssum)
{
    int t = blockIdx.x * blockDim.x + threadIdx.x;
    if (t >= NN * NH) return;
    int n = t >> 3, h = t & 7;
    const float4* pf = reinterpret_cast<const float4*>(fs + (size_t)n * HID + h * DH);
    const float4* pd = reinterpret_cast<const float4*>(fd + (size_t)n * HID + h * DH);
    const float4* pa = reinterpret_cast<const float4*>(al + h * DH);
    const float4* pb = reinterpret_cast<const float4*>(ar + h * DH);
    float sl = 0.f, sr = 0.f;
#pragma unroll
    for (int i = 0; i < 4; i++) {
        float4 a = pf[i], w = pa[i];
        sl += a.x * w.x + a.y * w.y + a.z * w.z + a.w * w.w;
        float4 b = pd[i], v = pb[i];
        sr += b.x * v.x + b.y * v.y + b.z * v.z + b.w * v.w;
    }
    el[t] = sl;
    er[t] = sr;
    ssum[t] = 0.f;
}

// ---------------- edge pass 1: ex = exp(leaky_relu(el[s]+er[d])), ssum += ----
// NOTE: max-shift omitted; exp args are O(0.5) with these input scales, and
// softmax is shift-invariant, so the result is mathematically identical.
__global__ void edge_exp_kernel(const int* __restrict__ src, const int* __restrict__ dst,
                                const float* __restrict__ el, const float* __restrict__ er,
                                float* __restrict__ ex, float* __restrict__ ssum)
{
    int t = blockIdx.x * blockDim.x + threadIdx.x;
    if (t >= EE * NH) return;
    int e = t >> 3, h = t & 7;
    int s = src[e], d = dst[e];
    float v = el[s * NH + h] + er[d * NH + h];
    v = v > 0.f ? v : 0.2f * v;
    float ev = __expf(v);
    ex[t] = ev;
    atomicAdd(&ssum[d * NH + h], ev);
}

// ---------------- edge pass 2: z[dst,m,:] += fs[src,:] * alpha --------------
// one warp per edge; lane covers 4 consecutive floats; red.v4 scatter
__global__ void edge_scatter_kernel(const int* __restrict__ src, const int* __restrict__ dst,
                                    const float* __restrict__ fs, const float* __restrict__ ex,
                                    const float* __restrict__ ssum, float* __restrict__ zsl)
{
    int warp = (blockIdx.x * blockDim.x + threadIdx.x) >> 5;
    int lane = threadIdx.x & 31;
    if (warp >= EE) return;
    int s = src[warp], d = dst[warp];
    int h = lane >> 2;
    float alpha = ex[warp * NH + h] / fmaxf(ssum[d * NH + h], 1e-9f);
    float4 f = *reinterpret_cast<const float4*>(fs + (size_t)s * HID + lane * 4);
    float vx = f.x * alpha, vy = f.y * alpha, vz = f.z * alpha, vw = f.w * alpha;
    float* p = zsl + (size_t)d * (MM * HID) + lane * 4;
    asm volatile("red.global.add.v4.f32 [%0], {%1,%2,%3,%4};"
                 :: "l"(p), "f"(vx), "f"(vy), "f"(vz), "f"(vw) : "memory");
}

// ---------------- elementwise ELU over z ------------------------------------
__global__ void elu_kernel(float* __restrict__ z, int n)
{
    int i = blockIdx.x * blockDim.x + threadIdx.x;
    if (i < n) {
        float v = z[i];
        z[i] = v > 0.f ? v : (__expf(v) - 1.f);
    }
}

// ---------------- semantic dot: w[r] = t[r,:] . w_sem2 ----------------------
__global__ void wdot_kernel(const float* __restrict__ t, const float* __restrict__ w2,
                            float* __restrict__ w, int rows)
{
    int warp = (blockIdx.x * blockDim.x + threadIdx.x) >> 5;
    int lane = threadIdx.x & 31;
    if (warp >= rows) return;
    float4 tv = *reinterpret_cast<const float4*>(t + (size_t)warp * HID + lane * 4);
    float4 wv = *reinterpret_cast<const float4*>(w2 + lane * 4);
    float p = tv.x * wv.x + tv.y * wv.y + tv.z * wv.z + tv.w * wv.w;
#pragma unroll
    for (int off = 16; off; off >>= 1) p += __shfl_down_sync(0xffffffffu, p, off);
    if (lane == 0) w[warp] = p;
}

// ---------------- final: beta softmax, fuse, output GEMV --------------------
__global__ void final_kernel(const float* __restrict__ w, const float* __restrict__ z,
                             const float* __restrict__ Wout, const float* __restrict__ bout,
                             float* __restrict__ out)
{
    __shared__ float sW[HID * OUTD];
    for (int i = threadIdx.x; i < HID * OUTD; i += blockDim.x) sW[i] = Wout[i];
    __syncthreads();
    int warp = (blockIdx.x * blockDim.x + threadIdx.x) >> 5;
    int lane = threadIdx.x & 31;
    if (warp >= NN) return;
    float w0 = w[warp * 3 + 0], w1 = w[warp * 3 + 1], w2 = w[warp * 3 + 2];
    float mx = fmaxf(w0, fmaxf(w1, w2));
    float e0 = __expf(w0 - mx), e1 = __expf(w1 - mx), e2 = __expf(w2 - mx);
    float inv = 1.f / (e0 + e1 + e2);
    float b0 = e0 * inv, b1 = e1 * inv, b2 = e2 * inv;
    const float* zr = z + (size_t)warp * (MM * HID);
    float4 z0 = *reinterpret_cast<const float4*>(zr + lane * 4);
    float4 z1 = *reinterpret_cast<const float4*>(zr + HID + lane * 4);
    float4 z2 = *reinterpret_cast<const float4*>(zr + 2 * HID + lane * 4);
    float f[4];
    f[0] = b0 * z0.x + b1 * z1.x + b2 * z2.x;
    f[1] = b0 * z0.y + b1 * z1.y + b2 * z2.y;
    f[2] = b0 * z0.z + b1 * z1.z + b2 * z2.z;
    f[3] = b0 * z0.w + b1 * z1.w + b2 * z2.w;
    float po[OUTD];
#pragma unroll
    for (int o = 0; o < OUTD; o++) {
        po[o] = 0.f;
#pragma unroll
        for (int j = 0; j < 4; j++)
            po[o] += f[j] * sW[(lane * 4 + j) * OUTD + o];
    }
#pragma unroll
    for (int off = 16; off; off >>= 1)
#pragma unroll
        for (int o = 0; o < OUTD; o++)
            po[o] += __shfl_down_sync(0xffffffffu, po[o], off);
    if (lane == 0)
#pragma unroll
        for (int o = 0; o < OUTD; o++)
            out[(size_t)warp * OUTD + o] = po[o] + bout[o];
}

// ---------------- launch --------------------------------------------------
extern "C" void kernel_launch(void* const* d_in, const int* in_sizes, int n_in,
                              void* d_out, int out_size)
{
    const float* features = (const float*)d_in[0];
    const float* W_fc     = (const float*)d_in[1];
    const float* b_fc     = (const float*)d_in[2];
    const float* W_src    = (const float*)d_in[3];
    const float* W_dst    = (const float*)d_in[4];
    const float* attn_l   = (const float*)d_in[5];
    const float* attn_r   = (const float*)d_in[6];
    const float* W_sem1   = (const float*)d_in[7];
    const float* b_sem1   = (const float*)d_in[8];
    const float* w_sem2   = (const float*)d_in[9];
    const float* W_out    = (const float*)d_in[10];
    const float* b_out    = (const float*)d_in[11];
    const int*   src_idx  = (const int*)d_in[12];
    const int*   dst_idx  = (const int*)d_in[13];
    float* out = (float*)d_out;

    float *h, *fs, *fd, *el, *er, *ss, *ex, *z, *t, *w;
    cudaGetSymbolAddress((void**)&h,  d_h);
    cudaGetSymbolAddress((void**)&fs, d_fs);
    cudaGetSymbolAddress((void**)&fd, d_fd);
    cudaGetSymbolAddress((void**)&el, d_el);
    cudaGetSymbolAddress((void**)&er, d_er);
    cudaGetSymbolAddress((void**)&ss, d_ss);
    cudaGetSymbolAddress((void**)&ex, d_ex);
    cudaGetSymbolAddress((void**)&z,  d_z);
    cudaGetSymbolAddress((void**)&t,  d_t);
    cudaGetSymbolAddress((void**)&w,  d_w);

    cudaMemsetAsync(z, 0, (size_t)NN * MM * HID * sizeof(float));

    // h = features @ W_fc + b_fc
    sgemm128<<<(NN + BM - 1) / BM, 256>>>(features, W_fc, b_fc, h, NN, F_IN, 0);

    for (int m = 0; m < MM; m++) {
        const float* Ws = W_src + (size_t)m * HID * HID;
        const float* Wd = W_dst + (size_t)m * HID * HID;
        const float* al = attn_l + (size_t)m * NH * DH;
        const float* ar = attn_r + (size_t)m * NH * DH;
        const int* sidx = src_idx + (size_t)m * EE;
        const int* didx = dst_idx + (size_t)m * EE;

        sgemm128<<<(NN + BM - 1) / BM, 256>>>(h, Ws, nullptr, fs, NN, HID, 0);
        sgemm128<<<(NN + BM - 1) / BM, 256>>>(h, Wd, nullptr, fd, NN, HID, 0);
        elr_kernel<<<(NN * NH + 255) / 256, 256>>>(fs, fd, al, ar, el, er, ss);
        edge_exp_kernel<<<(EE * NH + 255) / 256, 256>>>(sidx, didx, el, er, ex, ss);
        edge_scatter_kernel<<<(EE + 7) / 8, 256>>>(sidx, didx, fs, ex, ss, z + m * HID);
    }

    elu_kernel<<<(NN * MM * HID + 255) / 256, 256>>>(z, NN * MM * HID);

    // t = tanh(z2 @ W_sem1 + b_sem1), z2 = (N*M, HID)
    sgemm128<<<(NN * MM + BM - 1) / BM, 256>>>(z, W_sem1, b_sem1, t, NN * MM, HID, 1);
    wdot_kernel<<<(NN * MM + 7) / 8, 256>>>(t, w_sem2, w, NN * MM);
    final_kernel<<<(NN + 7) / 8, 256>>>(w, z, W_out, b_out, out);
}

// round 2
// speedup vs baseline: 1.1016x; 1.1016x over previous
#include <cuda_runtime.h>
#include <cuda_bf16.h>
#include <cstdint>

#define NN   50000
#define F_IN 256
#define HID  128
#define NH   8
#define EE   800000
#define MM   3
#define OUTD 8
#define BM   64
#define BK   16

// ---------------- scratch (device globals; no allocation) ----------------
__device__ float d_h [NN * HID];
__device__ float d_fs[(size_t)MM * NN * HID];
__device__ float d_fd[(size_t)MM * NN * HID];
__device__ float d_el[(size_t)MM * NN * NH];
__device__ float d_er[(size_t)MM * NN * NH];
__device__ float d_ss[(size_t)MM * NN * NH];
__device__ float d_ex[(size_t)MM * EE * NH];
__device__ float d_z [(size_t)NN * MM * HID];
__device__ float d_w [NN * MM];

__device__ __forceinline__ void ffma2(unsigned long long &d,
                                      unsigned long long a,
                                      unsigned long long b)
{
    asm("fma.rn.f32x2 %0, %1, %2, %3;" : "=l"(d) : "l"(a), "l"(b), "l"(d));
}

__device__ __forceinline__ float elu1(float v)
{
    return v > 0.f ? v : (__expf(v) - 1.f);
}

// ---------------- f32x2 SGEMM, 128 output cols, fused epilogues ------------
// mode 0: C = A@B + bias                      (fc layer)
// mode 1: batched proj (grid.y = m*2+sd): C = A@B ; also el/er = head-dot
// mode 2: semantic: A' = elu(A); p = tanh(A'@B + bias) . w2 -> wout (no C)
__global__ void __launch_bounds__(256) gemm2(
    const float* __restrict__ A,
    const float* __restrict__ Wsrc, const float* __restrict__ Wdst,
    const float* __restrict__ bias,
    float* __restrict__ Cs, float* __restrict__ Cd,
    const float* __restrict__ attl, const float* __restrict__ attr,
    float* __restrict__ elo, float* __restrict__ ero,
    const float* __restrict__ w2, float* __restrict__ wout,
    int Mrows, int K, int mode)
{
    __shared__ __align__(16) float2 As2[BK][BM];
    __shared__ __align__(16) float  Bs [BK][HID];

    const int tid = threadIdx.x;
    const int tx = tid & 15;
    const int ty = tid >> 4;
    const int rowBase = blockIdx.x * BM;

    const float* B; float* C; const float* av; float* eo;
    if (mode == 1) {
        int m = blockIdx.y >> 1, sd = blockIdx.y & 1;
        B  = (sd ? Wdst : Wsrc) + (size_t)m * HID * HID;
        C  = (sd ? Cd : Cs)     + (size_t)m * NN * HID;
        av = (sd ? attr : attl) + (size_t)m * HID;
        eo = (sd ? ero : elo)   + (size_t)m * NN * NH;
    } else { B = Wsrc; C = Cs; av = nullptr; eo = nullptr; }

    const int arow = tid >> 2;
    const int acol = (tid & 3) * 4;
    const int brow = tid >> 5;
    const int bcol = (tid & 31) * 4;

    unsigned long long acc[4][4];
#pragma unroll
    for (int i = 0; i < 4; i++)
#pragma unroll
        for (int j = 0; j < 4; j++) acc[i][j] = 0ull;

    // prologue prefetch of tile 0
    float4 aReg = make_float4(0.f, 0.f, 0.f, 0.f);
    {
        int gr = rowBase + arow;
        if (gr < Mrows) aReg = *reinterpret_cast<const float4*>(A + (size_t)gr * K + acol);
    }
    float4 bReg0 = *reinterpret_cast<const float4*>(B + (size_t)brow * HID + bcol);
    float4 bReg1 = *reinterpret_cast<const float4*>(B + (size_t)(brow + 8) * HID + bcol);

    for (int k0 = 0; k0 < K; k0 += BK) {
        float4 a = aReg;
        if (mode == 2) { a.x = elu1(a.x); a.y = elu1(a.y); a.z = elu1(a.z); a.w = elu1(a.w); }
        As2[acol + 0][arow] = make_float2(a.x, a.x);
        As2[acol + 1][arow] = make_float2(a.y, a.y);
        As2[acol + 2][arow] = make_float2(a.z, a.z);
        As2[acol + 3][arow] = make_float2(a.w, a.w);
        *reinterpret_cast<float4*>(&Bs[brow][bcol])     = bReg0;
        *reinterpret_cast<float4*>(&Bs[brow + 8][bcol]) = bReg1;
        __syncthreads();

        if (k0 + BK < K) {
            int gr = rowBase + arow;
            if (gr < Mrows)
                aReg = *reinterpret_cast<const float4*>(A + (size_t)gr * K + k0 + BK + acol);
            bReg0 = *reinterpret_cast<const float4*>(B + (size_t)(k0 + BK + brow) * HID + bcol);
            bReg1 = *reinterpret_cast<const float4*>(B + (size_t)(k0 + BK + brow + 8) * HID + bcol);
        }

#pragma unroll
        for (int kk = 0; kk < BK; kk++) {
            ulonglong2 a01 = *reinterpret_cast<const ulonglong2*>(&As2[kk][ty * 4]);
            ulonglong2 a23 = *reinterpret_cast<const ulonglong2*>(&As2[kk][ty * 4 + 2]);
            ulonglong2 b01 = *reinterpret_cast<const ulonglong2*>(&Bs[kk][tx * 8]);
            ulonglong2 b23 = *reinterpret_cast<const ulonglong2*>(&Bs[kk][tx * 8 + 4]);
            ffma2(acc[0][0], a01.x, b01.x); ffma2(acc[0][1], a01.x, b01.y);
            ffma2(acc[0][2], a01.x, b23.x); ffma2(acc[0][3], a01.x, b23.y);
            ffma2(acc[1][0], a01.y, b01.x); ffma2(acc[1][1], a01.y, b01.y);
            ffma2(acc[1][2], a01.y, b23.x); ffma2(acc[1][3], a01.y, b23.y);
            ffma2(acc[2][0], a23.x, b01.x); ffma2(acc[2][1], a23.x, b01.y);
            ffma2(acc[2][2], a23.x, b23.x); ffma2(acc[2][3], a23.x, b23.y);
            ffma2(acc[3][0], a23.y, b01.x); ffma2(acc[3][1], a23.y, b01.y);
            ffma2(acc[3][2], a23.y, b23.x); ffma2(acc[3][3], a23.y, b23.y);
        }
        __syncthreads();
    }

    // unpack accumulators
    float c[4][8];
#pragma unroll
    for (int i = 0; i < 4; i++)
#pragma unroll
        for (int j = 0; j < 4; j++) {
            float2 v = *reinterpret_cast<float2*>(&acc[i][j]);
            c[i][2 * j]     = v.x;
            c[i][2 * j + 1] = v.y;
        }

    const int r0 = rowBase + ty * 4;

    if (mode == 0) {
#pragma unroll
        for (int i = 0; i < 4; i++) {
            int r = r0 + i;
            if (r >= Mrows) break;
#pragma unroll
            for (int j = 0; j < 8; j++) c[i][j] += bias[tx * 8 + j];
            *reinterpret_cast<float4*>(C + (size_t)r * HID + tx * 8)     = *reinterpret_cast<float4*>(&c[i][0]);
            *reinterpret_cast<float4*>(C + (size_t)r * HID + tx * 8 + 4) = *reinterpret_cast<float4*>(&c[i][4]);
        }
    } else if (mode == 1) {
        // store projected features + fused attention logit dot per head
        float4 av0 = *reinterpret_cast<const float4*>(av + tx * 8);
        float4 av1 = *reinterpret_cast<const float4*>(av + tx * 8 + 4);
        float avv[8] = {av0.x, av0.y, av0.z, av0.w, av1.x, av1.y, av1.z, av1.w};
        int h = tx >> 1;
#pragma unroll
        for (int i = 0; i < 4; i++) {
            int r = r0 + i;
            bool ok = r < Mrows;
            if (ok) {
                *reinterpret_cast<float4*>(C + (size_t)r * HID + tx * 8)     = *reinterpret_cast<float4*>(&c[i][0]);
                *reinterpret_cast<float4*>(C + (size_t)r * HID + tx * 8 + 4) = *reinterpret_cast<float4*>(&c[i][4]);
            }
            float p = 0.f;
#pragma unroll
            for (int j = 0; j < 8; j++) p += c[i][j] * avv[j];
            p += __shfl_xor_sync(0xffffffffu, p, 1);
            if (ok && !(tx & 1)) eo[(size_t)r * NH + h] = p;
        }
    } else {
        // tanh(C + bias) . w2 -> wout, no C store
        float bloc[8], wloc[8];
#pragma unroll
        for (int j = 0; j < 8; j++) { bloc[j] = bias[tx * 8 + j]; wloc[j] = w2[tx * 8 + j]; }
#pragma unroll
        for (int i = 0; i < 4; i++) {
            int r = r0 + i;
            float p = 0.f;
#pragma unroll
            for (int j = 0; j < 8; j++) p += tanhf(c[i][j] + bloc[j]) * wloc[j];
            p += __shfl_xor_sync(0xffffffffu, p, 1);
            p += __shfl_xor_sync(0xffffffffu, p, 2);
            p += __shfl_xor_sync(0xffffffffu, p, 4);
            p += __shfl_xor_sync(0xffffffffu, p, 8);
            if (tx == 0 && r < Mrows) wout[r] = p;
        }
    }
}

// ---------------- edge pass 1 (all metapaths): ex + ssum atomics ------------
// max-shift omitted: softmax is shift-invariant and exp args are O(1) here.
__global__ void edge_exp_kernel(const int* __restrict__ src, const int* __restrict__ dst,
                                const float* __restrict__ el, const float* __restrict__ er,
                                float* __restrict__ ex, float* __restrict__ ss)
{
    int t = blockIdx.x * blockDim.x + threadIdx.x;
    if (t >= MM * EE * NH) return;
    int m = t / (EE * NH);
    int rem = t - m * (EE * NH);
    int e = rem >> 3, h = rem & 7;
    int s = src[(size_t)m * EE + e], d = dst[(size_t)m * EE + e];
    float v = el[((size_t)m * NN + s) * NH + h] + er[((size_t)m * NN + d) * NH + h];
    v = v > 0.f ? v : 0.2f * v;
    float ev = __expf(v);
    ex[t] = ev;
    atomicAdd(&ss[((size_t)m * NN + d) * NH + h], ev);
}

// ---------------- edge pass 2 (all metapaths): weighted scatter -------------
__global__ void edge_scatter_kernel(const int* __restrict__ src, const int* __restrict__ dst,
                                    const float* __restrict__ fs, const float* __restrict__ ex,
                                    const float* __restrict__ ss, float* __restrict__ z)
{
    int gw = (blockIdx.x * blockDim.x + threadIdx.x) >> 5;
    int lane = threadIdx.x & 31;
    if (gw >= MM * EE) return;
    int m = gw / EE;
    int e = gw - m * EE;
    int s = src[(size_t)m * EE + e], d = dst[(size_t)m * EE + e];
    int h = lane >> 2;
    float alpha = ex[(size_t)gw * NH + h] / fmaxf(ss[((size_t)m * NN + d) * NH + h], 1e-9f);
    float4 f = *reinterpret_cast<const float4*>(fs + ((size_t)m * NN + s) * HID + lane * 4);
    float vx = f.x * alpha, vy = f.y * alpha, vz = f.z * alpha, vw = f.w * alpha;
    float* p = z + ((size_t)d * MM + m) * HID + lane * 4;
    asm volatile("red.global.add.v4.f32 [%0], {%1,%2,%3,%4};"
                 :: "l"(p), "f"(vx), "f"(vy), "f"(vz), "f"(vw) : "memory");
}

// ---------------- final: beta softmax over w, elu(z) fuse, output GEMV ------
__global__ void final_kernel(const float* __restrict__ w, const float* __restrict__ z,
                             const float* __restrict__ Wout, const float* __restrict__ bout,
                             float* __restrict__ out)
{
    __shared__ float sW[HID * OUTD];
    for (int i = threadIdx.x; i < HID * OUTD; i += blockDim.x) sW[i] = Wout[i];
    __syncthreads();
    int warp = (blockIdx.x * blockDim.x + threadIdx.x) >> 5;
    int lane = threadIdx.x & 31;
    if (warp >= NN) return;
    float w0 = w[warp * 3 + 0], w1 = w[warp * 3 + 1], w2 = w[warp * 3 + 2];
    float mx = fmaxf(w0, fmaxf(w1, w2));
    float e0 = __expf(w0 - mx), e1 = __expf(w1 - mx), e2 = __expf(w2 - mx);
    float inv = 1.f / (e0 + e1 + e2);
    float b0 = e0 * inv, b1 = e1 * inv, b2 = e2 * inv;
    const float* zr = z + (size_t)warp * (MM * HID);
    float4 z0 = *reinterpret_cast<const float4*>(zr + lane * 4);
    float4 z1 = *reinterpret_cast<const float4*>(zr + HID + lane * 4);
    float4 z2 = *reinterpret_cast<const float4*>(zr + 2 * HID + lane * 4);
    float f[4];
    f[0] = b0 * elu1(z0.x) + b1 * elu1(z1.x) + b2 * elu1(z2.x);
    f[1] = b0 * elu1(z0.y) + b1 * elu1(z1.y) + b2 * elu1(z2.y);
    f[2] = b0 * elu1(z0.z) + b1 * elu1(z1.z) + b2 * elu1(z2.z);
    f[3] = b0 * elu1(z0.w) + b1 * elu1(z1.w) + b2 * elu1(z2.w);
    float po[OUTD];
#pragma unroll
    for (int o = 0; o < OUTD; o++) {
        po[o] = 0.f;
#pragma unroll
        for (int j = 0; j < 4; j++)
            po[o] += f[j] * sW[(lane * 4 + j) * OUTD + o];
    }
#pragma unroll
    for (int off = 16; off; off >>= 1)
#pragma unroll
        for (int o = 0; o < OUTD; o++)
            po[o] += __shfl_down_sync(0xffffffffu, po[o], off);
    if (lane == 0)
#pragma unroll
        for (int o = 0; o < OUTD; o++)
            out[(size_t)warp * OUTD + o] = po[o] + bout[o];
}

// ---------------- launch ----------------------------------------------------
extern "C" void kernel_launch(void* const* d_in, const int* in_sizes, int n_in,
                              void* d_out, int out_size)
{
    const float* features = (const float*)d_in[0];
    const float* W_fc     = (const float*)d_in[1];
    const float* b_fc     = (const float*)d_in[2];
    const float* W_src    = (const float*)d_in[3];
    const float* W_dst    = (const float*)d_in[4];
    const float* attn_l   = (const float*)d_in[5];
    const float* attn_r   = (const float*)d_in[6];
    const float* W_sem1   = (const float*)d_in[7];
    const float* b_sem1   = (const float*)d_in[8];
    const float* w_sem2   = (const float*)d_in[9];
    const float* W_out    = (const float*)d_in[10];
    const float* b_out    = (const float*)d_in[11];
    const int*   src_idx  = (const int*)d_in[12];
    const int*   dst_idx  = (const int*)d_in[13];
    float* out = (float*)d_out;

    float *h, *fs, *fd, *el, *er, *ss, *ex, *z, *w;
    cudaGetSymbolAddress((void**)&h,  d_h);
    cudaGetSymbolAddress((void**)&fs, d_fs);
    cudaGetSymbolAddress((void**)&fd, d_fd);
    cudaGetSymbolAddress((void**)&el, d_el);
    cudaGetSymbolAddress((void**)&er, d_er);
    cudaGetSymbolAddress((void**)&ss, d_ss);
    cudaGetSymbolAddress((void**)&ex, d_ex);
    cudaGetSymbolAddress((void**)&z,  d_z);
    cudaGetSymbolAddress((void**)&w,  d_w);

    cudaMemsetAsync(ss, 0, (size_t)MM * NN * NH * sizeof(float));
    cudaMemsetAsync(z,  0, (size_t)NN * MM * HID * sizeof(float));

    const int MT = (NN + BM - 1) / BM;

    // h = features @ W_fc + b_fc
    gemm2<<<dim3(MT, 1), 256>>>(features, W_fc, nullptr, b_fc, h, nullptr,
                                nullptr, nullptr, nullptr, nullptr, nullptr, nullptr,
                                NN, F_IN, 0);

    // all 6 projections + fused el/er in one launch
    gemm2<<<dim3(MT, 6), 256>>>(h, W_src, W_dst, nullptr, fs, fd,
                                attn_l, attn_r, el, er, nullptr, nullptr,
                                NN, HID, 1);

    edge_exp_kernel<<<(MM * EE * NH + 255) / 256, 256>>>(src_idx, dst_idx, el, er, ex, ss);
    edge_scatter_kernel<<<(MM * EE * 32 + 255) / 256, 256>>>(src_idx, dst_idx, fs, ex, ss, z);

    // semantic attention: w = tanh(elu(z) @ W_sem1 + b_sem1) . w_sem2
    gemm2<<<dim3((NN * MM + BM - 1) / BM, 1), 256>>>(z, W_sem1, nullptr, b_sem1,
                                nullptr, nullptr, nullptr, nullptr, nullptr, nullptr,
                                w_sem2, w, NN * MM, HID, 2);

    final_kernel<<<(NN + 7) / 8, 256>>>(w, z, W_out, b_out, out);
}

// round 4
// speedup vs baseline: 1.2273x; 1.1141x over previous
#include <cuda_runtime.h>
#include <cuda_bf16.h>
#include <cstdint>

#define NN   50000
#define F_IN 256
#define HID  128
#define NH   8
#define EE   800000
#define MM   3
#define OUTD 8
#define BM   64
#define BK   16
#define SEGS (MM * NN)

// ---------------- scratch (device globals; no allocation) ----------------
__device__ float d_h [NN * HID];
__device__ float d_fs[(size_t)MM * NN * HID];
__device__ float d_el[(size_t)MM * NN * NH];
__device__ float d_er[(size_t)MM * NN * NH];
__device__ float d_vd[MM * NH * HID];
__device__ float d_z [(size_t)NN * MM * HID];
__device__ float d_w [NN * MM];
__device__ int   d_cnt [SEGS];
__device__ int   d_off [SEGS];
__device__ int   d_pos [SEGS];
__device__ int   d_ssrc[MM * EE];

__device__ __forceinline__ void ffma2(unsigned long long &d,
                                      unsigned long long a,
                                      unsigned long long b)
{
    asm("fma.rn.f32x2 %0, %1, %2, %3;" : "=l"(d) : "l"(a), "l"(b), "l"(d));
}

__device__ __forceinline__ float elu1(float v)
{
    return v > 0.f ? v : (__expf(v) - 1.f);
}

// ---------------- f32x2 SGEMM, 128 output cols, fused epilogues ------------
// mode 0: C = A@B + bias                       (fc layer)
// mode 1: batched over grid.y = m: C = A@B ; fused el = head-dot with att
// mode 2: semantic: A' = elu(A); p = tanh(A'@B + bias) . w2 -> wout (no C)
__global__ void __launch_bounds__(256) gemm2(
    const float* __restrict__ A, const float* __restrict__ Bw,
    const float* __restrict__ bias, float* __restrict__ Cb,
    const float* __restrict__ att, float* __restrict__ elb,
    const float* __restrict__ w2, float* __restrict__ wout,
    int Mrows, int K, int mode)
{
    __shared__ __align__(16) float2 As2[BK][BM];
    __shared__ __align__(16) float  Bs [BK][HID];

    const int tid = threadIdx.x;
    const int tx = tid & 15;
    const int ty = tid >> 4;
    const int rowBase = blockIdx.x * BM;

    const float* B = Bw; float* C = Cb; const float* av = nullptr; float* eo = nullptr;
    if (mode == 1) {
        int m = blockIdx.y;
        B  = Bw  + (size_t)m * HID * HID;
        C  = Cb  + (size_t)m * NN * HID;
        av = att + (size_t)m * HID;
        eo = elb + (size_t)m * NN * NH;
    }

    const int arow = tid >> 2;
    const int acol = (tid & 3) * 4;
    const int brow = tid >> 5;
    const int bcol = (tid & 31) * 4;

    unsigned long long acc[4][4];
#pragma unroll
    for (int i = 0; i < 4; i++)
#pragma unroll
        for (int j = 0; j < 4; j++) acc[i][j] = 0ull;

    float4 aReg = make_float4(0.f, 0.f, 0.f, 0.f);
    {
        int gr = rowBase + arow;
        if (gr < Mrows) aReg = *reinterpret_cast<const float4*>(A + (size_t)gr * K + acol);
    }
    float4 bReg0 = *reinterpret_cast<const float4*>(B + (size_t)brow * HID + bcol);
    float4 bReg1 = *reinterpret_cast<const float4*>(B + (size_t)(brow + 8) * HID + bcol);

    for (int k0 = 0; k0 < K; k0 += BK) {
        float4 a = aReg;
        if (mode == 2) { a.x = elu1(a.x); a.y = elu1(a.y); a.z = elu1(a.z); a.w = elu1(a.w); }
        As2[acol + 0][arow] = make_float2(a.x, a.x);
        As2[acol + 1][arow] = make_float2(a.y, a.y);
        As2[acol + 2][arow] = make_float2(a.z, a.z);
        As2[acol + 3][arow] = make_float2(a.w, a.w);
        *reinterpret_cast<float4*>(&Bs[brow][bcol])     = bReg0;
        *reinterpret_cast<float4*>(&Bs[brow + 8][bcol]) = bReg1;
        __syncthreads();

        if (k0 + BK < K) {
            int gr = rowBase + arow;
            if (gr < Mrows)
                aReg = *reinterpret_cast<const float4*>(A + (size_t)gr * K + k0 + BK + acol);
            bReg0 = *reinterpret_cast<const float4*>(B + (size_t)(k0 + BK + brow) * HID + bcol);
            bReg1 = *reinterpret_cast<const float4*>(B + (size_t)(k0 + BK + brow + 8) * HID + bcol);
        }

#pragma unroll
        for (int kk = 0; kk < BK; kk++) {
            ulonglong2 a01 = *reinterpret_cast<const ulonglong2*>(&As2[kk][ty * 4]);
            ulonglong2 a23 = *reinterpret_cast<const ulonglong2*>(&As2[kk][ty * 4 + 2]);
            ulonglong2 b01 = *reinterpret_cast<const ulonglong2*>(&Bs[kk][tx * 8]);
            ulonglong2 b23 = *reinterpret_cast<const ulonglong2*>(&Bs[kk][tx * 8 + 4]);
            ffma2(acc[0][0], a01.x, b01.x); ffma2(acc[0][1], a01.x, b01.y);
            ffma2(acc[0][2], a01.x, b23.x); ffma2(acc[0][3], a01.x, b23.y);
            ffma2(acc[1][0], a01.y, b01.x); ffma2(acc[1][1], a01.y, b01.y);
            ffma2(acc[1][2], a01.y, b23.x); ffma2(acc[1][3], a01.y, b23.y);
            ffma2(acc[2][0], a23.x, b01.x); ffma2(acc[2][1], a23.x, b01.y);
            ffma2(acc[2][2], a23.x, b23.x); ffma2(acc[2][3], a23.x, b23.y);
            ffma2(acc[3][0], a23.y, b01.x); ffma2(acc[3][1], a23.y, b01.y);
            ffma2(acc[3][2], a23.y, b23.x); ffma2(acc[3][3], a23.y, b23.y);
        }
        __syncthreads();
    }

    float c[4][8];
#pragma unroll
    for (int i = 0; i < 4; i++)
#pragma unroll
        for (int j = 0; j < 4; j++) {
            float2 v = *reinterpret_cast<float2*>(&acc[i][j]);
            c[i][2 * j]     = v.x;
            c[i][2 * j + 1] = v.y;
        }

    const int r0 = rowBase + ty * 4;

    if (mode == 0) {
#pragma unroll
        for (int i = 0; i < 4; i++) {
            int r = r0 + i;
            if (r >= Mrows) break;
#pragma unroll
            for (int j = 0; j < 8; j++) c[i][j] += bias[tx * 8 + j];
            *reinterpret_cast<float4*>(C + (size_t)r * HID + tx * 8)     = *reinterpret_cast<float4*>(&c[i][0]);
            *reinterpret_cast<float4*>(C + (size_t)r * HID + tx * 8 + 4) = *reinterpret_cast<float4*>(&c[i][4]);
        }
    } else if (mode == 1) {
        float4 av0 = *reinterpret_cast<const float4*>(av + tx * 8);
        float4 av1 = *reinterpret_cast<const float4*>(av + tx * 8 + 4);
        float avv[8] = {av0.x, av0.y, av0.z, av0.w, av1.x, av1.y, av1.z, av1.w};
        int h = tx >> 1;
#pragma unroll
        for (int i = 0; i < 4; i++) {
            int r = r0 + i;
            bool ok = r < Mrows;
            if (ok) {
                *reinterpret_cast<float4*>(C + (size_t)r * HID + tx * 8)     = *reinterpret_cast<float4*>(&c[i][0]);
                *reinterpret_cast<float4*>(C + (size_t)r * HID + tx * 8 + 4) = *reinterpret_cast<float4*>(&c[i][4]);
            }
            float p = 0.f;
#pragma unroll
            for (int j = 0; j < 8; j++) p += c[i][j] * avv[j];
            p += __shfl_xor_sync(0xffffffffu, p, 1);
            if (ok && !(tx & 1)) eo[(size_t)r * NH + h] = p;
        }
    } else {
        float bloc[8], wloc[8];
#pragma unroll
        for (int j = 0; j < 8; j++) { bloc[j] = bias[tx * 8 + j]; wloc[j] = w2[tx * 8 + j]; }
#pragma unroll
        for (int i = 0; i < 4; i++) {
            int r = r0 + i;
            float p = 0.f;
#pragma unroll
            for (int j = 0; j < 8; j++) p += tanhf(c[i][j] + bloc[j]) * wloc[j];
            p += __shfl_xor_sync(0xffffffffu, p, 1);
            p += __shfl_xor_sync(0xffffffffu, p, 2);
            p += __shfl_xor_sync(0xffffffffu, p, 4);
            p += __shfl_xor_sync(0xffffffffu, p, 8);
            if (tx == 0 && r < Mrows) wout[r] = p;
        }
    }
}

// ---------------- Vdst[m][h][k] = sum_d Wdst[m][k][h*16+d] * ar[m][h][d] ----
__global__ void vdst_kernel(const float* __restrict__ Wdst, const float* __restrict__ ar,
                            float* __restrict__ vd)
{
    int t = blockIdx.x * blockDim.x + threadIdx.x;
    if (t >= MM * NH * HID) return;
    int m = t / (NH * HID);
    int r = t - m * (NH * HID);
    int h = r / HID;
    int k = r - h * HID;
    const float* W = Wdst + ((size_t)m * HID + k) * HID + h * 16;
    const float* a = ar + (m * NH + h) * 16;
    float s = 0.f;
#pragma unroll
    for (int d = 0; d < 16; d++) s += W[d] * a[d];
    vd[(m * NH + h) * HID + k] = s;
}

// ---------------- er[m][n][h] = h_[n,:] . Vdst[m][h][:] ---------------------
// ONE WARP PER NODE (grid must supply NN warps)
__global__ void er_kernel(const float* __restrict__ hfeat, const float* __restrict__ vd,
                          float* __restrict__ er)
{
    __shared__ float sV[MM * NH * HID];
    for (int i = threadIdx.x; i < MM * NH * HID; i += blockDim.x) sV[i] = vd[i];
    __syncthreads();
    int warp = (blockIdx.x * blockDim.x + threadIdx.x) >> 5;
    int lane = threadIdx.x & 31;
    if (warp >= NN) return;
    float4 hv = *reinterpret_cast<const float4*>(hfeat + (size_t)warp * HID + lane * 4);
#pragma unroll
    for (int m = 0; m < MM; m++) {
#pragma unroll
        for (int hh = 0; hh < NH; hh++) {
            float4 vv = *reinterpret_cast<const float4*>(&sV[(m * NH + hh) * HID + lane * 4]);
            float p = hv.x * vv.x + hv.y * vv.y + hv.z * vv.z + hv.w * vv.w;
            p += __shfl_xor_sync(0xffffffffu, p, 16);
            p += __shfl_xor_sync(0xffffffffu, p, 8);
            p += __shfl_xor_sync(0xffffffffu, p, 4);
            p += __shfl_xor_sync(0xffffffffu, p, 2);
            p += __shfl_xor_sync(0xffffffffu, p, 1);
            if (lane == 0) er[((size_t)m * NN + warp) * NH + hh] = p;
        }
    }
}

// ---------------- CSR build: count / scan / fill ----------------------------
__global__ void count_kernel(const int* __restrict__ dst, int* __restrict__ cnt)
{
    int t = blockIdx.x * blockDim.x + threadIdx.x;
    if (t >= MM * EE) return;
    int m = t / EE;
    atomicAdd(&cnt[m * NN + dst[t]], 1);
}

#define SCAN_T 1024
#define SCAN_CH ((SEGS + SCAN_T - 1) / SCAN_T)
__global__ void __launch_bounds__(SCAN_T) scan_kernel(const int* __restrict__ cnt,
                                                      int* __restrict__ off,
                                                      int* __restrict__ pos)
{
    __shared__ int sm[SCAN_T];
    int tid = threadIdx.x;
    int base = tid * SCAN_CH;
    int s = 0;
    for (int i = 0; i < SCAN_CH; i++) {
        int idx = base + i;
        if (idx < SEGS) s += cnt[idx];
    }
    sm[tid] = s;
    __syncthreads();
    for (int d = 1; d < SCAN_T; d <<= 1) {
        int v = (tid >= d) ? sm[tid - d] : 0;
        __syncthreads();
        sm[tid] += v;
        __syncthreads();
    }
    int run = sm[tid] - s;  // exclusive prefix of this chunk
    for (int i = 0; i < SCAN_CH; i++) {
        int idx = base + i;
        if (idx < SEGS) {
            off[idx] = run;
            pos[idx] = run;
            run += cnt[idx];
        }
    }
}

__global__ void fill_kernel(const int* __restrict__ src, const int* __restrict__ dst,
                            int* __restrict__ pos, int* __restrict__ ssrc)
{
    int t = blockIdx.x * blockDim.x + threadIdx.x;
    if (t >= MM * EE) return;
    int m = t / EE;
    int p = atomicAdd(&pos[m * NN + dst[t]], 1);
    ssrc[p] = src[t];
}

// ---------------- gather: per (m, dst) warp: softmax + weighted aggregation -
__global__ void gather_kernel(const int* __restrict__ ssrc,
                              const int* __restrict__ off, const int* __restrict__ cnt,
                              const float* __restrict__ el, const float* __restrict__ er,
                              const float* __restrict__ fs, float* __restrict__ z)
{
    int gw = (blockIdx.x * blockDim.x + threadIdx.x) >> 5;
    int lane = threadIdx.x & 31;
    if (gw >= SEGS) return;
    int m = gw / NN;
    int n = gw - m * NN;
    int beg = off[gw];
    int num = cnt[gw];
    const float* elm = el + (size_t)m * NN * NH;
    const float* fsm = fs + (size_t)m * NN * HID;

    // pass 1: per-head exp-sum (no max shift; softmax is shift-invariant and
    // logits are O(1) with these weight scales)
    int h8 = lane & 7;
    float er8 = er[(size_t)gw * NH + h8];
    float ssum = 0.f;
    for (int it = (lane >> 3); it < num; it += 4) {
        int s = ssrc[beg + it];
        float v = elm[s * NH + h8] + er8;
        v = v > 0.f ? v : 0.2f * v;
        ssum += __expf(v);
    }
    ssum += __shfl_xor_sync(0xffffffffu, ssum, 8);
    ssum += __shfl_xor_sync(0xffffffffu, ssum, 16);
    // lane i<8 now holds head-i sum; remap to pass-2 head = lane>>2
    int h4 = lane >> 2;
    float ssum4 = __shfl_sync(0xffffffffu, ssum, h4);
    float er4   = __shfl_sync(0xffffffffu, er8, h4);
    float inv = 1.f / fmaxf(ssum4, 1e-9f);

    // pass 2: accumulate fs[src] * alpha into registers (no atomics)
    float4 acc = make_float4(0.f, 0.f, 0.f, 0.f);
    int s = (num > 0) ? ssrc[beg] : 0;
    for (int it = 0; it < num; ++it) {
        int snext = (it + 1 < num) ? ssrc[beg + it + 1] : 0;
        float v = elm[s * NH + h4] + er4;
        float4 f = *reinterpret_cast<const float4*>(fsm + (size_t)s * HID + lane * 4);
        v = v > 0.f ? v : 0.2f * v;
        float a = __expf(v) * inv;
        acc.x += f.x * a; acc.y += f.y * a; acc.z += f.z * a; acc.w += f.w * a;
        s = snext;
    }
    *reinterpret_cast<float4*>(z + ((size_t)n * MM + m) * HID + lane * 4) = acc;
}

// ---------------- final: beta softmax over w, elu(z) fuse, output GEMV ------
__global__ void final_kernel(const float* __restrict__ w, const float* __restrict__ z,
                             const float* __restrict__ Wout, const float* __restrict__ bout,
                             float* __restrict__ out)
{
    __shared__ float sW[HID * OUTD];
    for (int i = threadIdx.x; i < HID * OUTD; i += blockDim.x) sW[i] = Wout[i];
    __syncthreads();
    int warp = (blockIdx.x * blockDim.x + threadIdx.x) >> 5;
    int lane = threadIdx.x & 31;
    if (warp >= NN) return;
    float w0 = w[warp * 3 + 0], w1 = w[warp * 3 + 1], w2 = w[warp * 3 + 2];
    float mx = fmaxf(w0, fmaxf(w1, w2));
    float e0 = __expf(w0 - mx), e1 = __expf(w1 - mx), e2 = __expf(w2 - mx);
    float inv = 1.f / (e0 + e1 + e2);
    float b0 = e0 * inv, b1 = e1 * inv, b2 = e2 * inv;
    const float* zr = z + (size_t)warp * (MM * HID);
    float4 z0 = *reinterpret_cast<const float4*>(zr + lane * 4);
    float4 z1 = *reinterpret_cast<const float4*>(zr + HID + lane * 4);
    float4 z2 = *reinterpret_cast<const float4*>(zr + 2 * HID + lane * 4);
    float f[4];
    f[0] = b0 * elu1(z0.x) + b1 * elu1(z1.x) + b2 * elu1(z2.x);
    f[1] = b0 * elu1(z0.y) + b1 * elu1(z1.y) + b2 * elu1(z2.y);
    f[2] = b0 * elu1(z0.z) + b1 * elu1(z1.z) + b2 * elu1(z2.z);
    f[3] = b0 * elu1(z0.w) + b1 * elu1(z1.w) + b2 * elu1(z2.w);
    float po[OUTD];
#pragma unroll
    for (int o = 0; o < OUTD; o++) {
        po[o] = 0.f;
#pragma unroll
        for (int j = 0; j < 4; j++)
            po[o] += f[j] * sW[(lane * 4 + j) * OUTD + o];
    }
#pragma unroll
    for (int off = 16; off; off >>= 1)
#pragma unroll
        for (int o = 0; o < OUTD; o++)
            po[o] += __shfl_down_sync(0xffffffffu, po[o], off);
    if (lane == 0)
#pragma unroll
        for (int o = 0; o < OUTD; o++)
            out[(size_t)warp * OUTD + o] = po[o] + bout[o];
}

// ---------------- launch ----------------------------------------------------
extern "C" void kernel_launch(void* const* d_in, const int* in_sizes, int n_in,
                              void* d_out, int out_size)
{
    const float* features = (const float*)d_in[0];
    const float* W_fc     = (const float*)d_in[1];
    const float* b_fc     = (const float*)d_in[2];
    const float* W_src    = (const float*)d_in[3];
    const float* W_dst    = (const float*)d_in[4];
    const float* attn_l   = (const float*)d_in[5];
    const float* attn_r   = (const float*)d_in[6];
    const float* W_sem1   = (const float*)d_in[7];
    const float* b_sem1   = (const float*)d_in[8];
    const float* w_sem2   = (const float*)d_in[9];
    const float* W_out    = (const float*)d_in[10];
    const float* b_out    = (const float*)d_in[11];
    const int*   src_idx  = (const int*)d_in[12];
    const int*   dst_idx  = (const int*)d_in[13];
    float* out = (float*)d_out;

    float *h, *fs, *el, *er, *vd, *z, *w;
    int *cnt, *off, *pos, *ssrc;
    cudaGetSymbolAddress((void**)&h,   d_h);
    cudaGetSymbolAddress((void**)&fs,  d_fs);
    cudaGetSymbolAddress((void**)&el,  d_el);
    cudaGetSymbolAddress((void**)&er,  d_er);
    cudaGetSymbolAddress((void**)&vd,  d_vd);
    cudaGetSymbolAddress((void**)&z,   d_z);
    cudaGetSymbolAddress((void**)&w,   d_w);
    cudaGetSymbolAddress((void**)&cnt, d_cnt);
    cudaGetSymbolAddress((void**)&off, d_off);
    cudaGetSymbolAddress((void**)&pos, d_pos);
    cudaGetSymbolAddress((void**)&ssrc,d_ssrc);

    cudaMemsetAsync(cnt, 0, SEGS * sizeof(int));

    const int MT = (NN + BM - 1) / BM;

    // CSR build (independent of GEMMs)
    count_kernel<<<(MM * EE + 255) / 256, 256>>>(dst_idx, cnt);
    scan_kernel<<<1, SCAN_T>>>(cnt, off, pos);
    fill_kernel<<<(MM * EE + 255) / 256, 256>>>(src_idx, dst_idx, pos, ssrc);

    // h = features @ W_fc + b_fc
    gemm2<<<dim3(MT, 1), 256>>>(features, W_fc, b_fc, h, nullptr, nullptr,
                                nullptr, nullptr, NN, F_IN, 0);

    // fs[m] = h @ W_src[m] with fused el; er via factored Vdst
    vdst_kernel<<<(MM * NH * HID + 255) / 256, 256>>>(W_dst, attn_r, vd);
    gemm2<<<dim3(MT, MM), 256>>>(h, W_src, nullptr, fs, attn_l, el,
                                 nullptr, nullptr, NN, HID, 1);
    er_kernel<<<(NN + 7) / 8, 256>>>(h, vd, er);   // ONE WARP PER NODE (bug fix)

    // edge softmax + aggregation, atomic-free
    gather_kernel<<<(SEGS + 7) / 8, 256>>>(ssrc, off, cnt, el, er, fs, z);

    // semantic attention: w = tanh(elu(z) @ W_sem1 + b_sem1) . w_sem2
    gemm2<<<dim3((NN * MM + BM - 1) / BM, 1), 256>>>(z, W_sem1, b_sem1, nullptr,
                                nullptr, nullptr, w_sem2, w, NN * MM, HID, 2);

    final_kernel<<<(NN + 7) / 8, 256>>>(w, z, W_out, b_out, out);
}